// round 15
// baseline (speedup 1.0000x reference)
#include <cuda_runtime.h>
#include <math.h>

#define BB 64
#define LL 512
#define HLL 512
#define HSS 512
#define EE 256
#define KK 128
#define VV 128
#define CC 34
#define TT 200
#define TP1 201

#define NBLK 128
#define NTHR 512
#define NKSP 8

typedef unsigned long long u64;

// ---------------- smem layout (float offsets) ----------------
#define OFF_W1   0                 // [896][16]
#define OFF_W2   14336             // [1024][16]
#define OFF_WS   30720             // attend workspace (1792)
#define OFF_PART 32512             // [8][16][68] = 8704
#define OFF_C1   41216             // 256
#define OFF_C2   41472             // 256
#define OFF_B1   41728             // 16
#define OFF_B2   41744             // 16
#define SMEM_FLOATS 41760
#define SMEM_BYTES (SMEM_FLOATS * 4)

#define PSTR 68                    // partial j-stride
#define PSSZ 1088                  // 16*68

// ---------------- device scratch ----------------
__device__ __align__(16) float g_keypT[BB * KK * LL];    // [b][k][l]
__device__ __align__(16) float g_valp [BB * LL * VV];    // [b][l][v]
__device__ __align__(16) float g_embT [TT * EE * BB];    // [t][k][b]
__device__ __align__(16) float g_h1T[2][HSS * BB];       // [u][b]
__device__ __align__(16) float g_h2T[2][HSS * BB];
__device__ __align__(16) float g_ctxT[VV * BB];          // [v][b]
__device__ unsigned g_bar_cnt;
__device__ unsigned g_bar_gen;

// ---------------- init: transpose initial states ----------------
__global__ void init_kernel(const float* __restrict__ h1_0, const float* __restrict__ h2_0) {
    int i = blockIdx.x * blockDim.x + threadIdx.x;
    if (i < BB * HSS) {
        int b = i >> 9, u = i & 511;
        g_h1T[0][u * BB + b] = h1_0[i];
        g_h2T[0][u * BB + b] = h2_0[i];
    }
    if (i == 0) { g_bar_cnt = 0; g_bar_gen = 0; }
}

// ---------------- embedding gather+transpose for all steps ----------------
__global__ __launch_bounds__(256) void embT_kernel(const int* __restrict__ targets,
                                                   const float* __restrict__ embed) {
    __shared__ int tg[64];
    const int t = blockIdx.x;
    const int tid = threadIdx.x;
    if (tid < 64) tg[tid] = targets[tid * TP1 + t];
    __syncthreads();
    float* base = g_embT + (size_t)t * EE * BB;
    for (int idx = tid; idx < 64 * 64; idx += 256) {
        int b = idx & 63, kq = idx >> 6;
        float4 v = *reinterpret_cast<const float4*>(&embed[(size_t)tg[b] * EE + kq * 4]);
        float* dst = base + (size_t)(kq * 4) * BB + b;
        dst[0] = v.x; dst[64] = v.y; dst[128] = v.z; dst[192] = v.w;
    }
}

// ---------------- precompute keypT / valp (proven) --------------
__global__ __launch_bounds__(256) void precompute_kernel(
    const float* __restrict__ listener,
    const float* __restrict__ Wh, const float* __restrict__ bh,
    const float* __restrict__ Wv, const float* __restrict__ bv) {
    __shared__ __align__(16) float A_s[32][36];
    __shared__ __align__(16) float W_s[32][132];

    const int b   = blockIdx.z;
    const int ng  = blockIdx.y;
    const int l0t = blockIdx.x * 32;
    const int tid = threadIdx.x;
    const float* W    = ng ? Wv : Wh;
    const float* bias = ng ? bv : bh;

    const int n0 = (tid & 31) * 4;
    const int l0 = (tid >> 5) * 4;
    float acc[4][4] = {};

    for (int kc = 0; kc < HLL; kc += 32) {
        #pragma unroll
        for (int it = 0; it < 4; ++it) {
            int idx = tid + it * 256;
            int k = idx & 31, l = idx >> 5;
            A_s[k][l] = listener[((size_t)b * LL + l0t + l) * HLL + kc + k];
        }
        #pragma unroll
        for (int it = 0; it < 16; ++it) {
            int idx = tid + it * 256;
            int k = idx & 31, n = idx >> 5;
            W_s[k][n] = W[(size_t)n * HLL + kc + k];
        }
        __syncthreads();
        #pragma unroll
        for (int k = 0; k < 32; ++k) {
            float4 a4 = *reinterpret_cast<const float4*>(&A_s[k][l0]);
            float4 w4 = *reinterpret_cast<const float4*>(&W_s[k][n0]);
            float al[4] = {a4.x, a4.y, a4.z, a4.w};
            float wn[4] = {w4.x, w4.y, w4.z, w4.w};
            #pragma unroll
            for (int i = 0; i < 4; ++i)
                #pragma unroll
                for (int j = 0; j < 4; ++j)
                    acc[i][j] += al[i] * wn[j];
        }
        __syncthreads();
    }

    float bn[4] = {bias[n0], bias[n0 + 1], bias[n0 + 2], bias[n0 + 3]};
    if (ng == 0) {
        #pragma unroll
        for (int j = 0; j < 4; ++j)
            #pragma unroll
            for (int i = 0; i < 4; ++i)
                g_keypT[(size_t)b * KK * LL + (size_t)(n0 + j) * LL + (l0t + l0 + i)] =
                    acc[i][j] + bn[j];
    } else {
        #pragma unroll
        for (int i = 0; i < 4; ++i)
            #pragma unroll
            for (int j = 0; j < 4; ++j)
                g_valp[(size_t)b * LL * VV + (size_t)(l0t + l0 + i) * VV + (n0 + j)] =
                    acc[i][j] + bn[j];
    }
}

// ---------------- grid barrier (single-thread fence, CG-style) --------------
__device__ __forceinline__ void gridbar() {
    __syncthreads();                 // orders all CTA threads' writes before tid0's fence
    if (threadIdx.x == 0) {
        __threadfence();             // release: make CTA writes gpu-visible
        unsigned gen = *(volatile unsigned*)&g_bar_gen;
        if (atomicAdd(&g_bar_cnt, 1u) == NBLK - 1) {
            g_bar_cnt = 0;
            __threadfence();
            *(volatile unsigned*)&g_bar_gen = gen + 1;
        } else {
            while (*(volatile unsigned*)&g_bar_gen == gen) __nanosleep(32);
        }
        __threadfence();             // acquire: invalidate L1 before post-barrier reads
    }
    __syncthreads();
}

__device__ __forceinline__ float sigf(float x) { return 1.f / (1.f + expf(-x)); }

// ---------------- f32x2 helpers ----------------
__device__ __forceinline__ void fma2(u64& acc, u64 a, u64 w) {
    asm("fma.rn.f32x2 %0, %1, %2, %0;" : "+l"(acc) : "l"(a), "l"(w));
}
__device__ __forceinline__ u64 pack2(float w) {
    u64 r;
    asm("mov.b64 %0, {%1, %1};" : "=l"(r) : "f"(w));
    return r;
}

// compute 4 k-rows (a0..a3 = A pairs for rows r..r+3) against W rows at wbase
#define GEMM4(a0, a1, a2, a3, wbase) do {                                         \
    float4 w0 = *reinterpret_cast<const float4*>(wbase);                          \
    float4 w1 = *reinterpret_cast<const float4*>((wbase) + 16);                   \
    float4 w2 = *reinterpret_cast<const float4*>((wbase) + 32);                   \
    float4 w3 = *reinterpret_cast<const float4*>((wbase) + 48);                   \
    u64 d;                                                                        \
    d = pack2(w0.x); fma2(acc[0][0], (a0).x, d); fma2(acc[0][1], (a0).y, d);      \
    d = pack2(w0.y); fma2(acc[1][0], (a0).x, d); fma2(acc[1][1], (a0).y, d);      \
    d = pack2(w0.z); fma2(acc[2][0], (a0).x, d); fma2(acc[2][1], (a0).y, d);      \
    d = pack2(w0.w); fma2(acc[3][0], (a0).x, d); fma2(acc[3][1], (a0).y, d);      \
    d = pack2(w1.x); fma2(acc[0][0], (a1).x, d); fma2(acc[0][1], (a1).y, d);      \
    d = pack2(w1.y); fma2(acc[1][0], (a1).x, d); fma2(acc[1][1], (a1).y, d);      \
    d = pack2(w1.z); fma2(acc[2][0], (a1).x, d); fma2(acc[2][1], (a1).y, d);      \
    d = pack2(w1.w); fma2(acc[3][0], (a1).x, d); fma2(acc[3][1], (a1).y, d);      \
    d = pack2(w2.x); fma2(acc[0][0], (a2).x, d); fma2(acc[0][1], (a2).y, d);      \
    d = pack2(w2.y); fma2(acc[1][0], (a2).x, d); fma2(acc[1][1], (a2).y, d);      \
    d = pack2(w2.z); fma2(acc[2][0], (a2).x, d); fma2(acc[2][1], (a2).y, d);      \
    d = pack2(w2.w); fma2(acc[3][0], (a2).x, d); fma2(acc[3][1], (a2).y, d);      \
    d = pack2(w3.x); fma2(acc[0][0], (a3).x, d); fma2(acc[0][1], (a3).y, d);      \
    d = pack2(w3.y); fma2(acc[1][0], (a3).x, d); fma2(acc[1][1], (a3).y, d);      \
    d = pack2(w3.z); fma2(acc[2][0], (a3).x, d); fma2(acc[2][1], (a3).y, d);      \
    d = pack2(w3.w); fma2(acc[3][0], (a3).x, d); fma2(acc[3][1], (a3).y, d);      \
} while (0)

// ---------------- GEMM region: acc += W[k][j0..3]^T * xT[k][b0..3] ----------
// 8-row software pipeline (two 4-row groups in flight). Region lengths are
// multiples of 8 rows for all call sites.
__device__ __forceinline__ void gemm_region(
    const float* __restrict__ xT,      // base such that row k lives at xT + k*64
    int lo, int hi,
    const float* __restrict__ Wsm,     // smem, row k at Wsm + k*16
    int jl0, int b0, u64 (&acc)[4][2]) {
    if (lo >= hi) return;
    const float* xp = xT + (size_t)lo * 64 + b0;
    const float* wp = Wsm + lo * 16 + jl0;
    ulonglong2 p0 = *reinterpret_cast<const ulonglong2*>(xp);
    ulonglong2 p1 = *reinterpret_cast<const ulonglong2*>(xp + 64);
    ulonglong2 p2 = *reinterpret_cast<const ulonglong2*>(xp + 128);
    ulonglong2 p3 = *reinterpret_cast<const ulonglong2*>(xp + 192);
    ulonglong2 q0 = *reinterpret_cast<const ulonglong2*>(xp + 256);
    ulonglong2 q1 = *reinterpret_cast<const ulonglong2*>(xp + 320);
    ulonglong2 q2 = *reinterpret_cast<const ulonglong2*>(xp + 384);
    ulonglong2 q3 = *reinterpret_cast<const ulonglong2*>(xp + 448);
    for (int k = lo; k < hi; k += 8) {
        GEMM4(p0, p1, p2, p3, wp);
        if (k + 8 < hi) {
            const float* xn = xp + 512;
            p0 = *reinterpret_cast<const ulonglong2*>(xn);
            p1 = *reinterpret_cast<const ulonglong2*>(xn + 64);
            p2 = *reinterpret_cast<const ulonglong2*>(xn + 128);
            p3 = *reinterpret_cast<const ulonglong2*>(xn + 192);
        }
        GEMM4(q0, q1, q2, q3, wp + 64);
        if (k + 8 < hi) {
            const float* xn = xp + 768;
            q0 = *reinterpret_cast<const ulonglong2*>(xn);
            q1 = *reinterpret_cast<const ulonglong2*>(xn + 64);
            q2 = *reinterpret_cast<const ulonglong2*>(xn + 128);
            q3 = *reinterpret_cast<const ulonglong2*>(xn + 192);
        }
        xp += 512; wp += 128;
    }
}

// ---------------- attend + logits (one block == one batch, 512 thr) --------
__device__ void attend_block(float* ws, const float* __restrict__ h2T, int b, int t,
                             const float* __restrict__ Ws, const float* __restrict__ bs,
                             const float* __restrict__ Wout, const float* __restrict__ bout,
                             const int* __restrict__ outputs_length,
                             float* __restrict__ out) {
    float* h2s  = ws;            // 512
    float* q    = ws + 512;      // 128
    float* attn = ws + 640;      // 512
    float* red  = ws + 1152;     // 512
    float* ctxs = ws + 1664;     // 128
    const int tid = threadIdx.x;
    const int lane = tid & 31, wid = tid >> 5;

    h2s[tid] = h2T[(size_t)tid * BB + b];
    __syncthreads();

    // q = h2 @ Ws^T + bs  (4 threads per row, float4)
    {
        int k = tid & 127, qtr = tid >> 7;
        const float4* wr = reinterpret_cast<const float4*>(Ws + (size_t)k * HSS + qtr * 128);
        const float4* hh = reinterpret_cast<const float4*>(h2s + qtr * 128);
        float s0 = 0.f, s1 = 0.f, s2 = 0.f, s3 = 0.f;
        #pragma unroll 8
        for (int j = 0; j < 32; ++j) {
            float4 w = wr[j], h = hh[j];
            s0 += w.x * h.x; s1 += w.y * h.y; s2 += w.z * h.z; s3 += w.w * h.w;
        }
        red[tid] = (s0 + s1) + (s2 + s3);
    }
    __syncthreads();
    if (tid < 128) q[tid] = red[tid] + red[tid + 128] + red[tid + 256] + red[tid + 384] + bs[tid];
    __syncthreads();

    const int len = (b == 0) ? LL : outputs_length[b];
    const int l = tid;
    const float* kp = g_keypT + (size_t)b * KK * LL + l;
    float ea = 0.f, eb = 0.f, ec = 0.f, ed = 0.f;
    #pragma unroll 8
    for (int k = 0; k < 128; k += 4) {
        ea += q[k]     * kp[(size_t)k * LL];
        eb += q[k + 1] * kp[(size_t)(k + 1) * LL];
        ec += q[k + 2] * kp[(size_t)(k + 2) * LL];
        ed += q[k + 3] * kp[(size_t)(k + 3) * LL];
    }
    float e = (ea + eb) + (ec + ed);

    float m = (l < len) ? e : -1e30f;
    #pragma unroll
    for (int o = 16; o > 0; o >>= 1) m = fmaxf(m, __shfl_xor_sync(0xffffffffu, m, o));
    if (lane == 0) red[wid] = m;
    __syncthreads();
    if (tid == 0) {
        float v = red[0];
        #pragma unroll
        for (int i = 1; i < 16; ++i) v = fmaxf(v, red[i]);
        red[16] = v;
    }
    __syncthreads();
    float mx = red[16];

    float pp = (l < len) ? expf(e - mx) : 0.f;
    float s = pp;
    #pragma unroll
    for (int o = 16; o > 0; o >>= 1) s += __shfl_xor_sync(0xffffffffu, s, o);
    if (lane == 0) red[wid] = s;
    __syncthreads();
    if (tid == 0) {
        float v = 0.f;
        #pragma unroll
        for (int i = 0; i < 16; ++i) v += red[i];
        red[17] = v;
    }
    __syncthreads();
    float inv = 1.f / fmaxf(red[17], 1e-12f);
    float a = pp * inv;
    attn[l] = a;
    if (t >= 0)
        out[(size_t)BB * TT * CC + ((size_t)b * TT + t) * LL + l] = a;
    __syncthreads();

    // ctx = attn @ valp (4 threads per v, 128 l each)
    {
        int v = tid & 127, qtr = tid >> 7;
        const float* ah  = attn + qtr * 128;
        const float* vph = g_valp + (size_t)b * LL * VV + v + (size_t)(qtr * 128) * VV;
        float s0 = 0.f, s1 = 0.f, s2 = 0.f, s3 = 0.f;
        #pragma unroll 4
        for (int ll = 0; ll < 128; ll += 4) {
            s0 += ah[ll]     * vph[(size_t)ll * VV];
            s1 += ah[ll + 1] * vph[(size_t)(ll + 1) * VV];
            s2 += ah[ll + 2] * vph[(size_t)(ll + 2) * VV];
            s3 += ah[ll + 3] * vph[(size_t)(ll + 3) * VV];
        }
        red[tid] = (s0 + s1) + (s2 + s3);
    }
    __syncthreads();
    if (tid < 128) {
        float c = red[tid] + red[tid + 128] + red[tid + 256] + red[tid + 384];
        ctxs[tid] = c;
        g_ctxT[(size_t)tid * BB + b] = c;   // transposed for GEMM-1
    }
    __syncthreads();

    // logits = [h2 | ctx] @ Wout^T + bout  (16 warps over 34 rows)
    if (t >= 0) {
        for (int c = wid; c < CC; c += 16) {
            const float* wr = Wout + (size_t)c * (HSS + VV);
            float sl = 0.f;
            #pragma unroll
            for (int j = lane; j < 512; j += 32) sl += wr[j] * h2s[j];
            #pragma unroll
            for (int j = lane; j < 128; j += 32) sl += wr[512 + j] * ctxs[j];
            #pragma unroll
            for (int o = 16; o > 0; o >>= 1) sl += __shfl_xor_sync(0xffffffffu, sl, o);
            if (lane == 0) out[((size_t)b * TT + t) * CC + c] = sl + bout[c];
        }
    }
}

// ---------------- persistent decoder ----------------
__global__ __launch_bounds__(NTHR, 1) void speller_persistent(
    const float* __restrict__ Wih1, const float* __restrict__ bih1,
    const float* __restrict__ Whh1, const float* __restrict__ bhh1,
    const float* __restrict__ Wih2, const float* __restrict__ bih2,
    const float* __restrict__ Whh2, const float* __restrict__ bhh2,
    const float* __restrict__ Ws, const float* __restrict__ bs,
    const float* __restrict__ Wout, const float* __restrict__ bout,
    const int* __restrict__ outputs_length,
    const float* __restrict__ c1_0, const float* __restrict__ c2_0,
    float* __restrict__ out) {
    extern __shared__ __align__(16) float sm[];
    float* smW1   = sm + OFF_W1;
    float* smW2   = sm + OFF_W2;
    float* smWS   = sm + OFF_WS;
    float* smPart = sm + OFF_PART;
    float* smC1   = sm + OFF_C1;
    float* smC2   = sm + OFF_C2;
    float* smB1   = sm + OFF_B1;
    float* smB2   = sm + OFF_B2;

    const int tid = threadIdx.x;
    const int bid = blockIdx.x;
    const int u0  = bid * 4;
    const int ksp = tid >> 6;                         // 0..7
    const int jl0 = ((tid >> 3) & 3) * 4;
    const int b0  = ((((tid >> 5) & 1) << 3) + (tid & 7)) * 4;
    const int ul  = (tid >> 6) & 3;                   // cell-phase role (tid<256)
    const int cb  = tid & 63;
    const int k0A = ksp * 112, k1A = k0A + 112;       // gemm1 split
    const int k0B = ksp * 128, k1B = k0B + 128;       // gemm2 split

    // ---- one-time weight / bias / c-state staging ----
    for (int lin = tid; lin < 896 * 16; lin += NTHR) {
        int jj = lin / 896, kg = lin % 896;
        int r = (jj >> 2) * HSS + u0 + (jj & 3);
        float w = (kg < 384) ? Wih1[(size_t)r * 384 + kg]
                             : Whh1[(size_t)r * HSS + kg - 384];
        smW1[kg * 16 + jj] = w;
    }
    for (int lin = tid; lin < 1024 * 16; lin += NTHR) {
        int jj = lin >> 10, kg = lin & 1023;
        int r = (jj >> 2) * HSS + u0 + (jj & 3);
        float w = (kg < 512) ? Wih2[(size_t)r * HSS + kg]
                             : Whh2[(size_t)r * HSS + kg - 512];
        smW2[kg * 16 + jj] = w;
    }
    if (tid < 16) {
        int r = (tid >> 2) * HSS + u0 + (tid & 3);
        smB1[tid] = bih1[r] + bhh1[r];
        smB2[tid] = bih2[r] + bhh2[r];
    }
    if (tid < 256) {
        smC1[tid] = c1_0[cb * HSS + u0 + ul];
        smC2[tid] = c2_0[cb * HSS + u0 + ul];
    }
    __syncthreads();

    u64 acc1[4][2];   // gemm1 accumulator, carried across barriers

    // ---- prologue: ctx0 = attend(h2_0) + G1pre(t=0) on emb0 + h1_0 ----
    if (bid < BB)
        attend_block(smWS, g_h2T[0], bid, -1, Ws, bs, Wout, bout, outputs_length, out);
    #pragma unroll
    for (int i = 0; i < 4; ++i) { acc1[i][0] = 0ull; acc1[i][1] = 0ull; }
    gemm_region(g_embT,              max(k0A, 0),   min(k1A, 256), smW1, jl0, b0, acc1);
    gemm_region(g_h1T[0] - 384 * BB, max(k0A, 384), min(k1A, 896), smW1, jl0, b0, acc1);
    gridbar();

    for (int t = 0; t < TT; ++t) {
        const int p = t & 1;
        float*       h1wT = g_h1T[1 - p];
        const float* h2rT = g_h2T[p];
        float*       h2wT = g_h2T[1 - p];

        // ===== phase A': finish gemm1 (ctx rows) + cell1 =====
        gemm_region(g_ctxT - 256 * BB, max(k0A, 256), min(k1A, 384), smW1, jl0, b0, acc1);
        #pragma unroll
        for (int i = 0; i < 4; ++i)
            *reinterpret_cast<ulonglong2*>(&smPart[ksp * PSSZ + (jl0 + i) * PSTR + b0]) =
                make_ulonglong2(acc1[i][0], acc1[i][1]);
        __syncthreads();
        if (tid < 256) {   // cell1
            float g[4];
            #pragma unroll
            for (int gate = 0; gate < 4; ++gate) {
                int jj = gate * 4 + ul;
                float s = smB1[jj];
                #pragma unroll
                for (int s2 = 0; s2 < NKSP; ++s2) s += smPart[s2 * PSSZ + jj * PSTR + cb];
                g[gate] = s;
            }
            float cp = smC1[tid];
            float cn = sigf(g[1]) * cp + sigf(g[0]) * tanhf(g[2]);
            float hn = sigf(g[3]) * tanhf(cn);
            smC1[tid] = cn;
            h1wT[(size_t)(u0 + ul) * BB + cb] = hn;   // coalesced
        }
        gridbar();   // h1(t) visible grid-wide

        // ===== phase B: gemm2 + cell2 + G1pre(t+1) (emb+h1, needs only h1(t)) =====
        {
            u64 acc2[4][2] = {};
            gemm_region(h1wT,            max(k0B, 0),   min(k1B, 512),  smW2, jl0, b0, acc2);
            gemm_region(h2rT - 512 * BB, max(k0B, 512), min(k1B, 1024), smW2, jl0, b0, acc2);
            #pragma unroll
            for (int i = 0; i < 4; ++i)
                *reinterpret_cast<ulonglong2*>(&smPart[ksp * PSSZ + (jl0 + i) * PSTR + b0]) =
                    make_ulonglong2(acc2[i][0], acc2[i][1]);
        }
        __syncthreads();
        // G1pre for step t+1: all 512 threads, independent of smPart/cell2
        #pragma unroll
        for (int i = 0; i < 4; ++i) { acc1[i][0] = 0ull; acc1[i][1] = 0ull; }
        if (t + 1 < TT) {
            const float* embt = g_embT + (size_t)(t + 1) * EE * BB;
            gemm_region(embt,            max(k0A, 0),   min(k1A, 256), smW1, jl0, b0, acc1);
            gemm_region(h1wT - 384 * BB, max(k0A, 384), min(k1A, 896), smW1, jl0, b0, acc1);
        }
        if (tid < 256) {   // cell2
            float g[4];
            #pragma unroll
            for (int gate = 0; gate < 4; ++gate) {
                int jj = gate * 4 + ul;
                float s = smB2[jj];
                #pragma unroll
                for (int s2 = 0; s2 < NKSP; ++s2) s += smPart[s2 * PSSZ + jj * PSTR + cb];
                g[gate] = s;
            }
            float cp = smC2[tid];
            float cn = sigf(g[1]) * cp + sigf(g[0]) * tanhf(g[2]);
            float hn = sigf(g[3]) * tanhf(cn);
            smC2[tid] = cn;
            h2wT[(size_t)(u0 + ul) * BB + cb] = hn;
        }
        gridbar();   // h2(t) visible grid-wide

        // ===== phase C: attend only (blocks 0..63; others pass through) =====
        if (bid < BB)
            attend_block(smWS, h2wT, bid, t, Ws, bs, Wout, bout, outputs_length, out);
        gridbar();   // ctx(t) visible grid-wide
    }
}

// ---------------- launch ----------------
extern "C" void kernel_launch(void* const* d_in, const int* in_sizes, int n_in,
                              void* d_out, int out_size) {
    const float* listener       = (const float*)d_in[0];
    const int*   outputs_length = (const int*)  d_in[1];
    const int*   targets        = (const int*)  d_in[2];
    const float* embed = (const float*)d_in[4];
    const float* Ws    = (const float*)d_in[5];
    const float* bs    = (const float*)d_in[6];
    const float* Wh    = (const float*)d_in[7];
    const float* bh    = (const float*)d_in[8];
    const float* Wv    = (const float*)d_in[9];
    const float* bv    = (const float*)d_in[10];
    const float* Wih1  = (const float*)d_in[11];
    const float* bih1  = (const float*)d_in[12];
    const float* Whh1  = (const float*)d_in[13];
    const float* bhh1  = (const float*)d_in[14];
    const float* Wih2  = (const float*)d_in[15];
    const float* bih2  = (const float*)d_in[16];
    const float* Whh2  = (const float*)d_in[17];
    const float* bhh2  = (const float*)d_in[18];
    const float* Wout  = (const float*)d_in[19];
    const float* bout  = (const float*)d_in[20];
    const float* h1_0  = (const float*)d_in[21];
    const float* c1_0  = (const float*)d_in[22];
    const float* h2_0  = (const float*)d_in[23];
    const float* c2_0  = (const float*)d_in[24];
    float* out = (float*)d_out;

    cudaFuncSetAttribute(speller_persistent,
                         cudaFuncAttributeMaxDynamicSharedMemorySize, SMEM_BYTES);

    init_kernel<<<(BB * HSS + 255) / 256, 256>>>(h1_0, h2_0);
    embT_kernel<<<TT, 256>>>(targets, embed);
    precompute_kernel<<<dim3(16, 2, 64), 256>>>(listener, Wh, bh, Wv, bv);
    speller_persistent<<<NBLK, NTHR, SMEM_BYTES>>>(
        Wih1, bih1, Whh1, bhh1,
        Wih2, bih2, Whh2, bhh2,
        Ws, bs, Wout, bout,
        outputs_length, c1_0, c2_0, out);
}

// round 16
// speedup vs baseline: 1.0274x; 1.0274x over previous
#include <cuda_runtime.h>
#include <math.h>

#define BB 64
#define LL 512
#define HLL 512
#define HSS 512
#define EE 256
#define KK 128
#define VV 128
#define CC 34
#define TT 200
#define TP1 201

#define NBLK 128
#define NTHR 512
#define NKSP 8

typedef unsigned long long u64;

// ---------------- smem layout (float offsets) ----------------
#define OFF_W1   0                 // [896][16]
#define OFF_W2   14336             // [1024][16]
#define OFF_WS   30720             // attend workspace (1792)
#define OFF_PART 32512             // [8][16][68] = 8704
#define OFF_C1   41216             // 256
#define OFF_C2   41472             // 256
#define OFF_B1   41728             // 16
#define OFF_B2   41744             // 16
#define SMEM_FLOATS 41760
#define SMEM_BYTES (SMEM_FLOATS * 4)

#define PSTR 68                    // partial j-stride
#define PSSZ 1088                  // 16*68

// ---------------- device scratch ----------------
__device__ __align__(16) float g_keypT[BB * KK * LL];    // [b][k][l]
__device__ __align__(16) float g_valp [BB * LL * VV];    // [b][l][v]
__device__ __align__(16) float g_embT [TT * EE * BB];    // [t][k][b]
__device__ __align__(16) float g_h1T[2][HSS * BB];       // [u][b]
__device__ __align__(16) float g_h2T[2][HSS * BB];
__device__ __align__(16) float g_ctxT[VV * BB];          // [v][b]
// two-level barrier: 8 group counters spread 256B apart + root + gen
__device__ __align__(256) unsigned g_bar_sub[8 * 64];    // [grp*64]
__device__ unsigned g_bar_root;
__device__ unsigned g_bar_gen;

// ---------------- init: transpose initial states ----------------
__global__ void init_kernel(const float* __restrict__ h1_0, const float* __restrict__ h2_0) {
    int i = blockIdx.x * blockDim.x + threadIdx.x;
    if (i < BB * HSS) {
        int b = i >> 9, u = i & 511;
        g_h1T[0][u * BB + b] = h1_0[i];
        g_h2T[0][u * BB + b] = h2_0[i];
    }
    if (i < 8 * 64) g_bar_sub[i] = 0;
    if (i == 0) { g_bar_root = 0; g_bar_gen = 0; }
}

// ---------------- embedding gather+transpose for all steps ----------------
__global__ __launch_bounds__(256) void embT_kernel(const int* __restrict__ targets,
                                                   const float* __restrict__ embed) {
    __shared__ int tg[64];
    const int t = blockIdx.x;
    const int tid = threadIdx.x;
    if (tid < 64) tg[tid] = targets[tid * TP1 + t];
    __syncthreads();
    float* base = g_embT + (size_t)t * EE * BB;
    for (int idx = tid; idx < 64 * 64; idx += 256) {
        int b = idx & 63, kq = idx >> 6;
        float4 v = *reinterpret_cast<const float4*>(&embed[(size_t)tg[b] * EE + kq * 4]);
        float* dst = base + (size_t)(kq * 4) * BB + b;
        dst[0] = v.x; dst[64] = v.y; dst[128] = v.z; dst[192] = v.w;
    }
}

// ---------------- precompute keypT / valp (proven) --------------
__global__ __launch_bounds__(256) void precompute_kernel(
    const float* __restrict__ listener,
    const float* __restrict__ Wh, const float* __restrict__ bh,
    const float* __restrict__ Wv, const float* __restrict__ bv) {
    __shared__ __align__(16) float A_s[32][36];
    __shared__ __align__(16) float W_s[32][132];

    const int b   = blockIdx.z;
    const int ng  = blockIdx.y;
    const int l0t = blockIdx.x * 32;
    const int tid = threadIdx.x;
    const float* W    = ng ? Wv : Wh;
    const float* bias = ng ? bv : bh;

    const int n0 = (tid & 31) * 4;
    const int l0 = (tid >> 5) * 4;
    float acc[4][4] = {};

    for (int kc = 0; kc < HLL; kc += 32) {
        #pragma unroll
        for (int it = 0; it < 4; ++it) {
            int idx = tid + it * 256;
            int k = idx & 31, l = idx >> 5;
            A_s[k][l] = listener[((size_t)b * LL + l0t + l) * HLL + kc + k];
        }
        #pragma unroll
        for (int it = 0; it < 16; ++it) {
            int idx = tid + it * 256;
            int k = idx & 31, n = idx >> 5;
            W_s[k][n] = W[(size_t)n * HLL + kc + k];
        }
        __syncthreads();
        #pragma unroll
        for (int k = 0; k < 32; ++k) {
            float4 a4 = *reinterpret_cast<const float4*>(&A_s[k][l0]);
            float4 w4 = *reinterpret_cast<const float4*>(&W_s[k][n0]);
            float al[4] = {a4.x, a4.y, a4.z, a4.w};
            float wn[4] = {w4.x, w4.y, w4.z, w4.w};
            #pragma unroll
            for (int i = 0; i < 4; ++i)
                #pragma unroll
                for (int j = 0; j < 4; ++j)
                    acc[i][j] += al[i] * wn[j];
        }
        __syncthreads();
    }

    float bn[4] = {bias[n0], bias[n0 + 1], bias[n0 + 2], bias[n0 + 3]};
    if (ng == 0) {
        #pragma unroll
        for (int j = 0; j < 4; ++j)
            #pragma unroll
            for (int i = 0; i < 4; ++i)
                g_keypT[(size_t)b * KK * LL + (size_t)(n0 + j) * LL + (l0t + l0 + i)] =
                    acc[i][j] + bn[j];
    } else {
        #pragma unroll
        for (int i = 0; i < 4; ++i)
            #pragma unroll
            for (int j = 0; j < 4; ++j)
                g_valp[(size_t)b * LL * VV + (size_t)(l0t + l0 + i) * VV + (n0 + j)] =
                    acc[i][j] + bn[j];
    }
}

// ---------------- two-level grid barrier (spread arrival counters) ---------
__device__ __forceinline__ void gridbar() {
    __syncthreads();                 // orders all CTA threads' writes before tid0's fence
    if (threadIdx.x == 0) {
        __threadfence();             // release: make CTA writes gpu-visible
        unsigned gen = *(volatile unsigned*)&g_bar_gen;
        int grp = blockIdx.x >> 4;   // 8 groups of 16 blocks
        // monotonic counters: no resets, no write-ordering hazards
        if ((atomicAdd(&g_bar_sub[grp * 64], 1u) & 15u) == 15u) {
            if ((atomicAdd(&g_bar_root, 1u) & 7u) == 7u) {
                __threadfence();
                *(volatile unsigned*)&g_bar_gen = gen + 1;
            }
        }
        while (*(volatile unsigned*)&g_bar_gen == gen) __nanosleep(32);
        __threadfence();             // acquire: invalidate L1 before post-barrier reads
    }
    __syncthreads();
}

__device__ __forceinline__ float sigf(float x) { return 1.f / (1.f + expf(-x)); }

// ---------------- f32x2 helpers ----------------
__device__ __forceinline__ void fma2(u64& acc, u64 a, u64 w) {
    asm("fma.rn.f32x2 %0, %1, %2, %0;" : "+l"(acc) : "l"(a), "l"(w));
}
__device__ __forceinline__ u64 pack2(float w) {
    u64 r;
    asm("mov.b64 %0, {%1, %1};" : "=l"(r) : "f"(w));
    return r;
}

// compute 4 k-rows (a0..a3 = A pairs for rows r..r+3) against W rows at wbase
#define GEMM4(a0, a1, a2, a3, wbase) do {                                         \
    float4 w0 = *reinterpret_cast<const float4*>(wbase);                          \
    float4 w1 = *reinterpret_cast<const float4*>((wbase) + 16);                   \
    float4 w2 = *reinterpret_cast<const float4*>((wbase) + 32);                   \
    float4 w3 = *reinterpret_cast<const float4*>((wbase) + 48);                   \
    u64 d;                                                                        \
    d = pack2(w0.x); fma2(acc[0][0], (a0).x, d); fma2(acc[0][1], (a0).y, d);      \
    d = pack2(w0.y); fma2(acc[1][0], (a0).x, d); fma2(acc[1][1], (a0).y, d);      \
    d = pack2(w0.z); fma2(acc[2][0], (a0).x, d); fma2(acc[2][1], (a0).y, d);      \
    d = pack2(w0.w); fma2(acc[3][0], (a0).x, d); fma2(acc[3][1], (a0).y, d);      \
    d = pack2(w1.x); fma2(acc[0][0], (a1).x, d); fma2(acc[0][1], (a1).y, d);      \
    d = pack2(w1.y); fma2(acc[1][0], (a1).x, d); fma2(acc[1][1], (a1).y, d);      \
    d = pack2(w1.z); fma2(acc[2][0], (a1).x, d); fma2(acc[2][1], (a1).y, d);      \
    d = pack2(w1.w); fma2(acc[3][0], (a1).x, d); fma2(acc[3][1], (a1).y, d);      \
    d = pack2(w2.x); fma2(acc[0][0], (a2).x, d); fma2(acc[0][1], (a2).y, d);      \
    d = pack2(w2.y); fma2(acc[1][0], (a2).x, d); fma2(acc[1][1], (a2).y, d);      \
    d = pack2(w2.z); fma2(acc[2][0], (a2).x, d); fma2(acc[2][1], (a2).y, d);      \
    d = pack2(w2.w); fma2(acc[3][0], (a2).x, d); fma2(acc[3][1], (a2).y, d);      \
    d = pack2(w3.x); fma2(acc[0][0], (a3).x, d); fma2(acc[0][1], (a3).y, d);      \
    d = pack2(w3.y); fma2(acc[1][0], (a3).x, d); fma2(acc[1][1], (a3).y, d);      \
    d = pack2(w3.z); fma2(acc[2][0], (a3).x, d); fma2(acc[2][1], (a3).y, d);      \
    d = pack2(w3.w); fma2(acc[3][0], (a3).x, d); fma2(acc[3][1], (a3).y, d);      \
} while (0)

// ---------------- GEMM region: acc += W[k][j0..3]^T * xT[k][b0..3] ----------
// 8-row software pipeline (two 4-row groups in flight). Region lengths are
// multiples of 8 rows for all call sites.
__device__ __forceinline__ void gemm_region(
    const float* __restrict__ xT,      // base such that row k lives at xT + k*64
    int lo, int hi,
    const float* __restrict__ Wsm,     // smem, row k at Wsm + k*16
    int jl0, int b0, u64 (&acc)[4][2]) {
    if (lo >= hi) return;
    const float* xp = xT + (size_t)lo * 64 + b0;
    const float* wp = Wsm + lo * 16 + jl0;
    ulonglong2 p0 = *reinterpret_cast<const ulonglong2*>(xp);
    ulonglong2 p1 = *reinterpret_cast<const ulonglong2*>(xp + 64);
    ulonglong2 p2 = *reinterpret_cast<const ulonglong2*>(xp + 128);
    ulonglong2 p3 = *reinterpret_cast<const ulonglong2*>(xp + 192);
    ulonglong2 q0 = *reinterpret_cast<const ulonglong2*>(xp + 256);
    ulonglong2 q1 = *reinterpret_cast<const ulonglong2*>(xp + 320);
    ulonglong2 q2 = *reinterpret_cast<const ulonglong2*>(xp + 384);
    ulonglong2 q3 = *reinterpret_cast<const ulonglong2*>(xp + 448);
    for (int k = lo; k < hi; k += 8) {
        GEMM4(p0, p1, p2, p3, wp);
        if (k + 8 < hi) {
            const float* xn = xp + 512;
            p0 = *reinterpret_cast<const ulonglong2*>(xn);
            p1 = *reinterpret_cast<const ulonglong2*>(xn + 64);
            p2 = *reinterpret_cast<const ulonglong2*>(xn + 128);
            p3 = *reinterpret_cast<const ulonglong2*>(xn + 192);
        }
        GEMM4(q0, q1, q2, q3, wp + 64);
        if (k + 8 < hi) {
            const float* xn = xp + 768;
            q0 = *reinterpret_cast<const ulonglong2*>(xn);
            q1 = *reinterpret_cast<const ulonglong2*>(xn + 64);
            q2 = *reinterpret_cast<const ulonglong2*>(xn + 128);
            q3 = *reinterpret_cast<const ulonglong2*>(xn + 192);
        }
        xp += 512; wp += 128;
    }
}

// ---------------- attend + logits (one block == one batch, 512 thr) --------
__device__ void attend_block(float* ws, const float* __restrict__ h2T, int b, int t,
                             const float* __restrict__ Ws, const float* __restrict__ bs,
                             const float* __restrict__ Wout, const float* __restrict__ bout,
                             const int* __restrict__ outputs_length,
                             float* __restrict__ out) {
    float* h2s  = ws;            // 512
    float* q    = ws + 512;      // 128
    float* attn = ws + 640;      // 512
    float* red  = ws + 1152;     // 512
    float* ctxs = ws + 1664;     // 128
    const int tid = threadIdx.x;
    const int lane = tid & 31, wid = tid >> 5;

    h2s[tid] = h2T[(size_t)tid * BB + b];
    __syncthreads();

    // q = h2 @ Ws^T + bs  (4 threads per row, float4)
    {
        int k = tid & 127, qtr = tid >> 7;
        const float4* wr = reinterpret_cast<const float4*>(Ws + (size_t)k * HSS + qtr * 128);
        const float4* hh = reinterpret_cast<const float4*>(h2s + qtr * 128);
        float s0 = 0.f, s1 = 0.f, s2 = 0.f, s3 = 0.f;
        #pragma unroll 8
        for (int j = 0; j < 32; ++j) {
            float4 w = wr[j], h = hh[j];
            s0 += w.x * h.x; s1 += w.y * h.y; s2 += w.z * h.z; s3 += w.w * h.w;
        }
        red[tid] = (s0 + s1) + (s2 + s3);
    }
    __syncthreads();
    if (tid < 128) q[tid] = red[tid] + red[tid + 128] + red[tid + 256] + red[tid + 384] + bs[tid];
    __syncthreads();

    const int len = (b == 0) ? LL : outputs_length[b];
    const int l = tid;
    const float* kp = g_keypT + (size_t)b * KK * LL + l;
    float ea = 0.f, eb = 0.f, ec = 0.f, ed = 0.f;
    #pragma unroll 8
    for (int k = 0; k < 128; k += 4) {
        ea += q[k]     * kp[(size_t)k * LL];
        eb += q[k + 1] * kp[(size_t)(k + 1) * LL];
        ec += q[k + 2] * kp[(size_t)(k + 2) * LL];
        ed += q[k + 3] * kp[(size_t)(k + 3) * LL];
    }
    float e = (ea + eb) + (ec + ed);

    float m = (l < len) ? e : -1e30f;
    #pragma unroll
    for (int o = 16; o > 0; o >>= 1) m = fmaxf(m, __shfl_xor_sync(0xffffffffu, m, o));
    if (lane == 0) red[wid] = m;
    __syncthreads();
    if (tid == 0) {
        float v = red[0];
        #pragma unroll
        for (int i = 1; i < 16; ++i) v = fmaxf(v, red[i]);
        red[16] = v;
    }
    __syncthreads();
    float mx = red[16];

    float pp = (l < len) ? expf(e - mx) : 0.f;
    float s = pp;
    #pragma unroll
    for (int o = 16; o > 0; o >>= 1) s += __shfl_xor_sync(0xffffffffu, s, o);
    if (lane == 0) red[wid] = s;
    __syncthreads();
    if (tid == 0) {
        float v = 0.f;
        #pragma unroll
        for (int i = 0; i < 16; ++i) v += red[i];
        red[17] = v;
    }
    __syncthreads();
    float inv = 1.f / fmaxf(red[17], 1e-12f);
    float a = pp * inv;
    attn[l] = a;
    if (t >= 0)
        out[(size_t)BB * TT * CC + ((size_t)b * TT + t) * LL + l] = a;
    __syncthreads();

    // ctx = attn @ valp (4 threads per v, 128 l each)
    {
        int v = tid & 127, qtr = tid >> 7;
        const float* ah  = attn + qtr * 128;
        const float* vph = g_valp + (size_t)b * LL * VV + v + (size_t)(qtr * 128) * VV;
        float s0 = 0.f, s1 = 0.f, s2 = 0.f, s3 = 0.f;
        #pragma unroll 4
        for (int ll = 0; ll < 128; ll += 4) {
            s0 += ah[ll]     * vph[(size_t)ll * VV];
            s1 += ah[ll + 1] * vph[(size_t)(ll + 1) * VV];
            s2 += ah[ll + 2] * vph[(size_t)(ll + 2) * VV];
            s3 += ah[ll + 3] * vph[(size_t)(ll + 3) * VV];
        }
        red[tid] = (s0 + s1) + (s2 + s3);
    }
    __syncthreads();
    if (tid < 128) {
        float c = red[tid] + red[tid + 128] + red[tid + 256] + red[tid + 384];
        ctxs[tid] = c;
        g_ctxT[(size_t)tid * BB + b] = c;   // transposed for GEMM-1
    }
    __syncthreads();

    // logits = [h2 | ctx] @ Wout^T + bout  (16 warps over 34 rows)
    if (t >= 0) {
        for (int c = wid; c < CC; c += 16) {
            const float* wr = Wout + (size_t)c * (HSS + VV);
            float sl = 0.f;
            #pragma unroll
            for (int j = lane; j < 512; j += 32) sl += wr[j] * h2s[j];
            #pragma unroll
            for (int j = lane; j < 128; j += 32) sl += wr[512 + j] * ctxs[j];
            #pragma unroll
            for (int o = 16; o > 0; o >>= 1) sl += __shfl_xor_sync(0xffffffffu, sl, o);
            if (lane == 0) out[((size_t)b * TT + t) * CC + c] = sl + bout[c];
        }
    }
}

// ---------------- persistent decoder ----------------
__global__ __launch_bounds__(NTHR, 1) void speller_persistent(
    const float* __restrict__ Wih1, const float* __restrict__ bih1,
    const float* __restrict__ Whh1, const float* __restrict__ bhh1,
    const float* __restrict__ Wih2, const float* __restrict__ bih2,
    const float* __restrict__ Whh2, const float* __restrict__ bhh2,
    const float* __restrict__ Ws, const float* __restrict__ bs,
    const float* __restrict__ Wout, const float* __restrict__ bout,
    const int* __restrict__ outputs_length,
    const float* __restrict__ c1_0, const float* __restrict__ c2_0,
    float* __restrict__ out) {
    extern __shared__ __align__(16) float sm[];
    float* smW1   = sm + OFF_W1;
    float* smW2   = sm + OFF_W2;
    float* smWS   = sm + OFF_WS;
    float* smPart = sm + OFF_PART;
    float* smC1   = sm + OFF_C1;
    float* smC2   = sm + OFF_C2;
    float* smB1   = sm + OFF_B1;
    float* smB2   = sm + OFF_B2;

    const int tid = threadIdx.x;
    const int bid = blockIdx.x;
    const int u0  = bid * 4;
    const int ksp = tid >> 6;                         // 0..7
    const int jl0 = ((tid >> 3) & 3) * 4;
    const int b0  = ((((tid >> 5) & 1) << 3) + (tid & 7)) * 4;
    const int ul  = (tid >> 6) & 3;                   // cell-phase role (tid<256)
    const int cb  = tid & 63;
    const int k0A = ksp * 112, k1A = k0A + 112;       // gemm1 split
    const int k0B = ksp * 128, k1B = k0B + 128;       // gemm2 split

    // ---- one-time weight / bias / c-state staging ----
    for (int lin = tid; lin < 896 * 16; lin += NTHR) {
        int jj = lin / 896, kg = lin % 896;
        int r = (jj >> 2) * HSS + u0 + (jj & 3);
        float w = (kg < 384) ? Wih1[(size_t)r * 384 + kg]
                             : Whh1[(size_t)r * HSS + kg - 384];
        smW1[kg * 16 + jj] = w;
    }
    for (int lin = tid; lin < 1024 * 16; lin += NTHR) {
        int jj = lin >> 10, kg = lin & 1023;
        int r = (jj >> 2) * HSS + u0 + (jj & 3);
        float w = (kg < 512) ? Wih2[(size_t)r * HSS + kg]
                             : Whh2[(size_t)r * HSS + kg - 512];
        smW2[kg * 16 + jj] = w;
    }
    if (tid < 16) {
        int r = (tid >> 2) * HSS + u0 + (tid & 3);
        smB1[tid] = bih1[r] + bhh1[r];
        smB2[tid] = bih2[r] + bhh2[r];
    }
    if (tid < 256) {
        smC1[tid] = c1_0[cb * HSS + u0 + ul];
        smC2[tid] = c2_0[cb * HSS + u0 + ul];
    }
    __syncthreads();

    // ---- ctx0 = attend(h2_0) ----
    if (bid < BB)
        attend_block(smWS, g_h2T[0], bid, -1, Ws, bs, Wout, bout, outputs_length, out);
    gridbar();

    for (int t = 0; t < TT; ++t) {
        const int p = t & 1;
        const float* h1rT = g_h1T[p];
        float*       h1wT = g_h1T[1 - p];
        const float* h2rT = g_h2T[p];
        float*       h2wT = g_h2T[1 - p];

        // ================= phase A: lstm1 gates + cell1 =================
        {
            u64 acc[4][2] = {};
            const float* embt = g_embT + (size_t)t * EE * BB;
            gemm_region(embt,              max(k0A, 0),   min(k1A, 256), smW1, jl0, b0, acc);
            gemm_region(g_ctxT - 256 * BB, max(k0A, 256), min(k1A, 384), smW1, jl0, b0, acc);
            gemm_region(h1rT   - 384 * BB, max(k0A, 384), min(k1A, 896), smW1, jl0, b0, acc);
            #pragma unroll
            for (int i = 0; i < 4; ++i)
                *reinterpret_cast<ulonglong2*>(&smPart[ksp * PSSZ + (jl0 + i) * PSTR + b0]) =
                    make_ulonglong2(acc[i][0], acc[i][1]);
        }
        __syncthreads();
        if (tid < 256) {   // cell1
            float g[4];
            #pragma unroll
            for (int gate = 0; gate < 4; ++gate) {
                int jj = gate * 4 + ul;
                float s = smB1[jj];
                #pragma unroll
                for (int s2 = 0; s2 < NKSP; ++s2) s += smPart[s2 * PSSZ + jj * PSTR + cb];
                g[gate] = s;
            }
            float cp = smC1[tid];
            float cn = sigf(g[1]) * cp + sigf(g[0]) * tanhf(g[2]);
            float hn = sigf(g[3]) * tanhf(cn);
            smC1[tid] = cn;
            h1wT[(size_t)(u0 + ul) * BB + cb] = hn;   // coalesced
        }
        gridbar();

        // ================= phase B: lstm2 gates + cell2 =================
        {
            u64 acc[4][2] = {};
            gemm_region(h1wT,            max(k0B, 0),   min(k1B, 512),  smW2, jl0, b0, acc);
            gemm_region(h2rT - 512 * BB, max(k0B, 512), min(k1B, 1024), smW2, jl0, b0, acc);
            #pragma unroll
            for (int i = 0; i < 4; ++i)
                *reinterpret_cast<ulonglong2*>(&smPart[ksp * PSSZ + (jl0 + i) * PSTR + b0]) =
                    make_ulonglong2(acc[i][0], acc[i][1]);
        }
        __syncthreads();
        if (tid < 256) {   // cell2
            float g[4];
            #pragma unroll
            for (int gate = 0; gate < 4; ++gate) {
                int jj = gate * 4 + ul;
                float s = smB2[jj];
                #pragma unroll
                for (int s2 = 0; s2 < NKSP; ++s2) s += smPart[s2 * PSSZ + jj * PSTR + cb];
                g[gate] = s;
            }
            float cp = smC2[tid];
            float cn = sigf(g[1]) * cp + sigf(g[0]) * tanhf(g[2]);
            float hn = sigf(g[3]) * tanhf(cn);
            smC2[tid] = cn;
            h2wT[(size_t)(u0 + ul) * BB + cb] = hn;
        }
        gridbar();

        // ================= phase C: attend + logits =================
        if (bid < BB)
            attend_block(smWS, h2wT, bid, t, Ws, bs, Wout, bout, outputs_length, out);
        gridbar();
    }
}

// ---------------- launch ----------------
extern "C" void kernel_launch(void* const* d_in, const int* in_sizes, int n_in,
                              void* d_out, int out_size) {
    const float* listener       = (const float*)d_in[0];
    const int*   outputs_length = (const int*)  d_in[1];
    const int*   targets        = (const int*)  d_in[2];
    const float* embed = (const float*)d_in[4];
    const float* Ws    = (const float*)d_in[5];
    const float* bs    = (const float*)d_in[6];
    const float* Wh    = (const float*)d_in[7];
    const float* bh    = (const float*)d_in[8];
    const float* Wv    = (const float*)d_in[9];
    const float* bv    = (const float*)d_in[10];
    const float* Wih1  = (const float*)d_in[11];
    const float* bih1  = (const float*)d_in[12];
    const float* Whh1  = (const float*)d_in[13];
    const float* bhh1  = (const float*)d_in[14];
    const float* Wih2  = (const float*)d_in[15];
    const float* bih2  = (const float*)d_in[16];
    const float* Whh2  = (const float*)d_in[17];
    const float* bhh2  = (const float*)d_in[18];
    const float* Wout  = (const float*)d_in[19];
    const float* bout  = (const float*)d_in[20];
    const float* h1_0  = (const float*)d_in[21];
    const float* c1_0  = (const float*)d_in[22];
    const float* h2_0  = (const float*)d_in[23];
    const float* c2_0  = (const float*)d_in[24];
    float* out = (float*)d_out;

    cudaFuncSetAttribute(speller_persistent,
                         cudaFuncAttributeMaxDynamicSharedMemorySize, SMEM_BYTES);

    init_kernel<<<(BB * HSS + 255) / 256, 256>>>(h1_0, h2_0);
    embT_kernel<<<TT, 256>>>(targets, embed);
    precompute_kernel<<<dim3(16, 2, 64), 256>>>(listener, Wh, bh, Wv, bv);
    speller_persistent<<<NBLK, NTHR, SMEM_BYTES>>>(
        Wih1, bih1, Whh1, bhh1,
        Wih2, bih2, Whh2, bhh2,
        Ws, bs, Wout, bout,
        outputs_length, c1_0, c2_0, out);
}

// round 17
// speedup vs baseline: 1.0932x; 1.0640x over previous
#include <cuda_runtime.h>
#include <math.h>

#define BB 64
#define LL 512
#define HLL 512
#define HSS 512
#define EE 256
#define KK 128
#define VV 128
#define CC 34
#define TT 200
#define TP1 201

#define NBLK 128
#define NTHR 512
#define NKSP 8

typedef unsigned long long u64;

// ---------------- smem layout (float offsets) ----------------
#define OFF_W1   0                 // [896][16]
#define OFF_W2   14336             // [1024][16]
#define OFF_WS   30720             // attend workspace (3328)
#define OFF_PART 34048             // [8][16][68] = 8704
#define OFF_C1   42752             // 256
#define OFF_C2   43008             // 256
#define OFF_B1   43264             // 16
#define OFF_B2   43280             // 16
#define SMEM_FLOATS 43296
#define SMEM_BYTES (SMEM_FLOATS * 4)

#define PSTR 68                    // partial j-stride
#define PSSZ 1088                  // 16*68

// ---------------- device scratch ----------------
__device__ __align__(16) float g_keypT[BB * KK * LL];    // [b][k][l]
__device__ __align__(16) float g_valp [BB * LL * VV];    // [b][l][v]
__device__ __align__(16) float g_embT [TT * EE * BB];    // [t][k][b]
__device__ __align__(16) float g_h1T[2][HSS * BB];       // [u][b]
__device__ __align__(16) float g_h2T[2][HSS * BB];
__device__ __align__(16) float g_ctxT[VV * BB];          // [v][b]
__device__ unsigned g_bar_cnt;
__device__ unsigned g_bar_gen;

// ---------------- init: transpose initial states ----------------
__global__ void init_kernel(const float* __restrict__ h1_0, const float* __restrict__ h2_0) {
    int i = blockIdx.x * blockDim.x + threadIdx.x;
    if (i < BB * HSS) {
        int b = i >> 9, u = i & 511;
        g_h1T[0][u * BB + b] = h1_0[i];
        g_h2T[0][u * BB + b] = h2_0[i];
    }
    if (i == 0) { g_bar_cnt = 0; g_bar_gen = 0; }
}

// ---------------- embedding gather+transpose for all steps ----------------
__global__ __launch_bounds__(256) void embT_kernel(const int* __restrict__ targets,
                                                   const float* __restrict__ embed) {
    __shared__ int tg[64];
    const int t = blockIdx.x;
    const int tid = threadIdx.x;
    if (tid < 64) tg[tid] = targets[tid * TP1 + t];
    __syncthreads();
    float* base = g_embT + (size_t)t * EE * BB;
    for (int idx = tid; idx < 64 * 64; idx += 256) {
        int b = idx & 63, kq = idx >> 6;
        float4 v = *reinterpret_cast<const float4*>(&embed[(size_t)tg[b] * EE + kq * 4]);
        float* dst = base + (size_t)(kq * 4) * BB + b;
        dst[0] = v.x; dst[64] = v.y; dst[128] = v.z; dst[192] = v.w;
    }
}

// ---------------- precompute keypT / valp (proven) --------------
__global__ __launch_bounds__(256) void precompute_kernel(
    const float* __restrict__ listener,
    const float* __restrict__ Wh, const float* __restrict__ bh,
    const float* __restrict__ Wv, const float* __restrict__ bv) {
    __shared__ __align__(16) float A_s[32][36];
    __shared__ __align__(16) float W_s[32][132];

    const int b   = blockIdx.z;
    const int ng  = blockIdx.y;
    const int l0t = blockIdx.x * 32;
    const int tid = threadIdx.x;
    const float* W    = ng ? Wv : Wh;
    const float* bias = ng ? bv : bh;

    const int n0 = (tid & 31) * 4;
    const int l0 = (tid >> 5) * 4;
    float acc[4][4] = {};

    for (int kc = 0; kc < HLL; kc += 32) {
        #pragma unroll
        for (int it = 0; it < 4; ++it) {
            int idx = tid + it * 256;
            int k = idx & 31, l = idx >> 5;
            A_s[k][l] = listener[((size_t)b * LL + l0t + l) * HLL + kc + k];
        }
        #pragma unroll
        for (int it = 0; it < 16; ++it) {
            int idx = tid + it * 256;
            int k = idx & 31, n = idx >> 5;
            W_s[k][n] = W[(size_t)n * HLL + kc + k];
        }
        __syncthreads();
        #pragma unroll
        for (int k = 0; k < 32; ++k) {
            float4 a4 = *reinterpret_cast<const float4*>(&A_s[k][l0]);
            float4 w4 = *reinterpret_cast<const float4*>(&W_s[k][n0]);
            float al[4] = {a4.x, a4.y, a4.z, a4.w};
            float wn[4] = {w4.x, w4.y, w4.z, w4.w};
            #pragma unroll
            for (int i = 0; i < 4; ++i)
                #pragma unroll
                for (int j = 0; j < 4; ++j)
                    acc[i][j] += al[i] * wn[j];
        }
        __syncthreads();
    }

    float bn[4] = {bias[n0], bias[n0 + 1], bias[n0 + 2], bias[n0 + 3]};
    if (ng == 0) {
        #pragma unroll
        for (int j = 0; j < 4; ++j)
            #pragma unroll
            for (int i = 0; i < 4; ++i)
                g_keypT[(size_t)b * KK * LL + (size_t)(n0 + j) * LL + (l0t + l0 + i)] =
                    acc[i][j] + bn[j];
    } else {
        #pragma unroll
        for (int i = 0; i < 4; ++i)
            #pragma unroll
            for (int j = 0; j < 4; ++j)
                g_valp[(size_t)b * LL * VV + (size_t)(l0t + l0 + i) * VV + (n0 + j)] =
                    acc[i][j] + bn[j];
    }
}

// ---------------- grid barrier (single-thread fence, CG-style) --------------
__device__ __forceinline__ void gridbar() {
    __syncthreads();                 // orders all CTA threads' writes before tid0's fence
    if (threadIdx.x == 0) {
        __threadfence();             // release: make CTA writes gpu-visible
        unsigned gen = *(volatile unsigned*)&g_bar_gen;
        if (atomicAdd(&g_bar_cnt, 1u) == NBLK - 1) {
            g_bar_cnt = 0;
            __threadfence();
            *(volatile unsigned*)&g_bar_gen = gen + 1;
        } else {
            while (*(volatile unsigned*)&g_bar_gen == gen) __nanosleep(32);
        }
        __threadfence();             // acquire: invalidate L1 before post-barrier reads
    }
    __syncthreads();
}

__device__ __forceinline__ float sigf(float x) { return 1.f / (1.f + expf(-x)); }

// ---------------- f32x2 helpers ----------------
__device__ __forceinline__ void fma2(u64& acc, u64 a, u64 w) {
    asm("fma.rn.f32x2 %0, %1, %2, %0;" : "+l"(acc) : "l"(a), "l"(w));
}
__device__ __forceinline__ u64 pack2(float w) {
    u64 r;
    asm("mov.b64 %0, {%1, %1};" : "=l"(r) : "f"(w));
    return r;
}

// compute 4 k-rows (a0..a3 = A pairs for rows r..r+3) against W rows at wbase
#define GEMM4(a0, a1, a2, a3, wbase) do {                                         \
    float4 w0 = *reinterpret_cast<const float4*>(wbase);                          \
    float4 w1 = *reinterpret_cast<const float4*>((wbase) + 16);                   \
    float4 w2 = *reinterpret_cast<const float4*>((wbase) + 32);                   \
    float4 w3 = *reinterpret_cast<const float4*>((wbase) + 48);                   \
    u64 d;                                                                        \
    d = pack2(w0.x); fma2(acc[0][0], (a0).x, d); fma2(acc[0][1], (a0).y, d);      \
    d = pack2(w0.y); fma2(acc[1][0], (a0).x, d); fma2(acc[1][1], (a0).y, d);      \
    d = pack2(w0.z); fma2(acc[2][0], (a0).x, d); fma2(acc[2][1], (a0).y, d);      \
    d = pack2(w0.w); fma2(acc[3][0], (a0).x, d); fma2(acc[3][1], (a0).y, d);      \
    d = pack2(w1.x); fma2(acc[0][0], (a1).x, d); fma2(acc[0][1], (a1).y, d);      \
    d = pack2(w1.y); fma2(acc[1][0], (a1).x, d); fma2(acc[1][1], (a1).y, d);      \
    d = pack2(w1.z); fma2(acc[2][0], (a1).x, d); fma2(acc[2][1], (a1).y, d);      \
    d = pack2(w1.w); fma2(acc[3][0], (a1).x, d); fma2(acc[3][1], (a1).y, d);      \
    d = pack2(w2.x); fma2(acc[0][0], (a2).x, d); fma2(acc[0][1], (a2).y, d);      \
    d = pack2(w2.y); fma2(acc[1][0], (a2).x, d); fma2(acc[1][1], (a2).y, d);      \
    d = pack2(w2.z); fma2(acc[2][0], (a2).x, d); fma2(acc[2][1], (a2).y, d);      \
    d = pack2(w2.w); fma2(acc[3][0], (a2).x, d); fma2(acc[3][1], (a2).y, d);      \
    d = pack2(w3.x); fma2(acc[0][0], (a3).x, d); fma2(acc[0][1], (a3).y, d);      \
    d = pack2(w3.y); fma2(acc[1][0], (a3).x, d); fma2(acc[1][1], (a3).y, d);      \
    d = pack2(w3.z); fma2(acc[2][0], (a3).x, d); fma2(acc[2][1], (a3).y, d);      \
    d = pack2(w3.w); fma2(acc[3][0], (a3).x, d); fma2(acc[3][1], (a3).y, d);      \
} while (0)

// ---------------- GEMM region: acc += W[k][j0..3]^T * xT[k][b0..3] ----------
// 8-row software pipeline (two 4-row groups in flight).
__device__ __forceinline__ void gemm_region(
    const float* __restrict__ xT,
    int lo, int hi,
    const float* __restrict__ Wsm,
    int jl0, int b0, u64 (&acc)[4][2]) {
    if (lo >= hi) return;
    const float* xp = xT + (size_t)lo * 64 + b0;
    const float* wp = Wsm + lo * 16 + jl0;
    ulonglong2 p0 = *reinterpret_cast<const ulonglong2*>(xp);
    ulonglong2 p1 = *reinterpret_cast<const ulonglong2*>(xp + 64);
    ulonglong2 p2 = *reinterpret_cast<const ulonglong2*>(xp + 128);
    ulonglong2 p3 = *reinterpret_cast<const ulonglong2*>(xp + 192);
    ulonglong2 q0 = *reinterpret_cast<const ulonglong2*>(xp + 256);
    ulonglong2 q1 = *reinterpret_cast<const ulonglong2*>(xp + 320);
    ulonglong2 q2 = *reinterpret_cast<const ulonglong2*>(xp + 384);
    ulonglong2 q3 = *reinterpret_cast<const ulonglong2*>(xp + 448);
    for (int k = lo; k < hi; k += 8) {
        GEMM4(p0, p1, p2, p3, wp);
        if (k + 8 < hi) {
            const float* xn = xp + 512;
            p0 = *reinterpret_cast<const ulonglong2*>(xn);
            p1 = *reinterpret_cast<const ulonglong2*>(xn + 64);
            p2 = *reinterpret_cast<const ulonglong2*>(xn + 128);
            p3 = *reinterpret_cast<const ulonglong2*>(xn + 192);
        }
        GEMM4(q0, q1, q2, q3, wp + 64);
        if (k + 8 < hi) {
            const float* xn = xp + 768;
            q0 = *reinterpret_cast<const ulonglong2*>(xn);
            q1 = *reinterpret_cast<const ulonglong2*>(xn + 64);
            q2 = *reinterpret_cast<const ulonglong2*>(xn + 128);
            q3 = *reinterpret_cast<const ulonglong2*>(xn + 192);
        }
        xp += 512; wp += 128;
    }
}

// ---------------- attend + logits (one block == one batch, 512 thr) --------
// Vectorized: float4 loads for energy (keypT) and ctx (valp).
__device__ void attend_block(float* ws, const float* __restrict__ h2T, int b, int t,
                             const float* __restrict__ Ws, const float* __restrict__ bs,
                             const float* __restrict__ Wout, const float* __restrict__ bout,
                             const int* __restrict__ outputs_length,
                             float* __restrict__ out) {
    float* h2s  = ws;            // 512
    float* q    = ws + 512;      // 128
    float* attn = ws + 640;      // 512
    float* ctxs = ws + 1152;     // 128
    float* red  = ws + 1280;     // 2048 (float4 x 512)
    float4* red4 = reinterpret_cast<float4*>(red);
    const int tid = threadIdx.x;
    const int lane = tid & 31, wid = tid >> 5;

    h2s[tid] = h2T[(size_t)tid * BB + b];
    __syncthreads();

    // q = h2 @ Ws^T + bs  (4 threads per row, float4)
    {
        int k = tid & 127, qtr = tid >> 7;
        const float4* wr = reinterpret_cast<const float4*>(Ws + (size_t)k * HSS + qtr * 128);
        const float4* hh = reinterpret_cast<const float4*>(h2s + qtr * 128);
        float s0 = 0.f, s1 = 0.f, s2 = 0.f, s3 = 0.f;
        #pragma unroll 8
        for (int j = 0; j < 32; ++j) {
            float4 w = wr[j], h = hh[j];
            s0 += w.x * h.x; s1 += w.y * h.y; s2 += w.z * h.z; s3 += w.w * h.w;
        }
        red[tid] = (s0 + s1) + (s2 + s3);
    }
    __syncthreads();
    if (tid < 128) q[tid] = red[tid] + red[tid + 128] + red[tid + 256] + red[tid + 384] + bs[tid];
    __syncthreads();

    // energy partials: (128 l-quads) x (4 k-chunks of 32)
    {
        int l4 = tid & 127, kc = tid >> 7;
        const float4* kp4 = reinterpret_cast<const float4*>(
            g_keypT + (size_t)b * KK * LL + (size_t)(kc * 32) * LL) + l4;
        const float* qq = q + kc * 32;
        float4 e = make_float4(0.f, 0.f, 0.f, 0.f);
        #pragma unroll 8
        for (int k = 0; k < 32; ++k) {
            float4 v = kp4[(size_t)k * 128];
            float qk = qq[k];
            e.x += qk * v.x; e.y += qk * v.y; e.z += qk * v.z; e.w += qk * v.w;
        }
        red4[kc * 128 + l4] = e;
    }
    __syncthreads();

    const int len = (b == 0) ? LL : outputs_length[b];
    float4 e4 = make_float4(0.f, 0.f, 0.f, 0.f);
    float4 p4 = make_float4(0.f, 0.f, 0.f, 0.f);
    if (tid < 128) {
        float4 a0 = red4[tid], a1 = red4[128 + tid], a2 = red4[256 + tid], a3 = red4[384 + tid];
        e4.x = (a0.x + a1.x) + (a2.x + a3.x);
        e4.y = (a0.y + a1.y) + (a2.y + a3.y);
        e4.z = (a0.z + a1.z) + (a2.z + a3.z);
        e4.w = (a0.w + a1.w) + (a2.w + a3.w);
    }
    __syncthreads();   // red free for reduction scratch

    if (tid < 128) {
        int l0 = tid * 4;
        float m = fmaxf(fmaxf((l0 < len)     ? e4.x : -1e30f,
                              (l0 + 1 < len) ? e4.y : -1e30f),
                        fmaxf((l0 + 2 < len) ? e4.z : -1e30f,
                              (l0 + 3 < len) ? e4.w : -1e30f));
        #pragma unroll
        for (int o = 16; o > 0; o >>= 1) m = fmaxf(m, __shfl_xor_sync(0xffffffffu, m, o));
        if (lane == 0) red[wid] = m;
    }
    __syncthreads();
    if (tid == 0) red[16] = fmaxf(fmaxf(red[0], red[1]), fmaxf(red[2], red[3]));
    __syncthreads();
    float mx = red[16];

    if (tid < 128) {
        int l0 = tid * 4;
        p4.x = (l0 < len)     ? expf(e4.x - mx) : 0.f;
        p4.y = (l0 + 1 < len) ? expf(e4.y - mx) : 0.f;
        p4.z = (l0 + 2 < len) ? expf(e4.z - mx) : 0.f;
        p4.w = (l0 + 3 < len) ? expf(e4.w - mx) : 0.f;
        float s = (p4.x + p4.y) + (p4.z + p4.w);
        #pragma unroll
        for (int o = 16; o > 0; o >>= 1) s += __shfl_xor_sync(0xffffffffu, s, o);
        if (lane == 0) red[wid] = s;
    }
    __syncthreads();
    if (tid == 0) red[17] = red[0] + red[1] + red[2] + red[3];
    __syncthreads();
    if (tid < 128) {
        float inv = 1.f / fmaxf(red[17], 1e-12f);
        float4 a4 = make_float4(p4.x * inv, p4.y * inv, p4.z * inv, p4.w * inv);
        reinterpret_cast<float4*>(attn)[tid] = a4;
        if (t >= 0)
            *reinterpret_cast<float4*>(
                out + (size_t)BB * TT * CC + ((size_t)b * TT + t) * LL + tid * 4) = a4;
    }
    __syncthreads();

    // ctx partials: (32 v-quads) x (16 l-chunks of 32)
    {
        int v4 = tid & 31, lc = tid >> 5;
        const float4* vp4 = reinterpret_cast<const float4*>(
            g_valp + (size_t)b * LL * VV + (size_t)(lc * 32) * VV) + v4;
        const float* ah = attn + lc * 32;
        float4 c = make_float4(0.f, 0.f, 0.f, 0.f);
        #pragma unroll 8
        for (int l = 0; l < 32; ++l) {
            float4 v = vp4[(size_t)l * 32];
            float a = ah[l];
            c.x += a * v.x; c.y += a * v.y; c.z += a * v.z; c.w += a * v.w;
        }
        red4[lc * 32 + v4] = c;
    }
    __syncthreads();
    if (tid < 32) {
        float4 c = make_float4(0.f, 0.f, 0.f, 0.f);
        #pragma unroll
        for (int lc = 0; lc < 16; ++lc) {
            float4 v = red4[lc * 32 + tid];
            c.x += v.x; c.y += v.y; c.z += v.z; c.w += v.w;
        }
        reinterpret_cast<float4*>(ctxs)[tid] = c;
        int v0 = tid * 4;
        g_ctxT[(size_t)v0 * BB + b]       = c.x;
        g_ctxT[(size_t)(v0 + 1) * BB + b] = c.y;
        g_ctxT[(size_t)(v0 + 2) * BB + b] = c.z;
        g_ctxT[(size_t)(v0 + 3) * BB + b] = c.w;
    }
    __syncthreads();

    // logits = [h2 | ctx] @ Wout^T + bout  (16 warps over 34 rows)
    if (t >= 0) {
        for (int c = wid; c < CC; c += 16) {
            const float* wr = Wout + (size_t)c * (HSS + VV);
            float sl = 0.f;
            #pragma unroll
            for (int j = lane; j < 512; j += 32) sl += wr[j] * h2s[j];
            #pragma unroll
            for (int j = lane; j < 128; j += 32) sl += wr[512 + j] * ctxs[j];
            #pragma unroll
            for (int o = 16; o > 0; o >>= 1) sl += __shfl_xor_sync(0xffffffffu, sl, o);
            if (lane == 0) out[((size_t)b * TT + t) * CC + c] = sl + bout[c];
        }
    }
}

// ---------------- persistent decoder ----------------
__global__ __launch_bounds__(NTHR, 1) void speller_persistent(
    const float* __restrict__ Wih1, const float* __restrict__ bih1,
    const float* __restrict__ Whh1, const float* __restrict__ bhh1,
    const float* __restrict__ Wih2, const float* __restrict__ bih2,
    const float* __restrict__ Whh2, const float* __restrict__ bhh2,
    const float* __restrict__ Ws, const float* __restrict__ bs,
    const float* __restrict__ Wout, const float* __restrict__ bout,
    const int* __restrict__ outputs_length,
    const float* __restrict__ c1_0, const float* __restrict__ c2_0,
    float* __restrict__ out) {
    extern __shared__ __align__(16) float sm[];
    float* smW1   = sm + OFF_W1;
    float* smW2   = sm + OFF_W2;
    float* smWS   = sm + OFF_WS;
    float* smPart = sm + OFF_PART;
    float* smC1   = sm + OFF_C1;
    float* smC2   = sm + OFF_C2;
    float* smB1   = sm + OFF_B1;
    float* smB2   = sm + OFF_B2;

    const int tid = threadIdx.x;
    const int bid = blockIdx.x;
    const int u0  = bid * 4;
    const int ksp = tid >> 6;                         // 0..7
    const int jl0 = ((tid >> 3) & 3) * 4;
    const int b0  = ((((tid >> 5) & 1) << 3) + (tid & 7)) * 4;
    const int ul  = (tid >> 6) & 3;                   // cell-phase role (tid<256)
    const int cb  = tid & 63;
    const int k0A = ksp * 112, k1A = k0A + 112;       // gemm1 split
    const int k0B = ksp * 128, k1B = k0B + 128;       // gemm2 split

    // ---- one-time weight / bias / c-state staging ----
    for (int lin = tid; lin < 896 * 16; lin += NTHR) {
        int jj = lin / 896, kg = lin % 896;
        int r = (jj >> 2) * HSS + u0 + (jj & 3);
        float w = (kg < 384) ? Wih1[(size_t)r * 384 + kg]
                             : Whh1[(size_t)r * HSS + kg - 384];
        smW1[kg * 16 + jj] = w;
    }
    for (int lin = tid; lin < 1024 * 16; lin += NTHR) {
        int jj = lin >> 10, kg = lin & 1023;
        int r = (jj >> 2) * HSS + u0 + (jj & 3);
        float w = (kg < 512) ? Wih2[(size_t)r * HSS + kg]
                             : Whh2[(size_t)r * HSS + kg - 512];
        smW2[kg * 16 + jj] = w;
    }
    if (tid < 16) {
        int r = (tid >> 2) * HSS + u0 + (tid & 3);
        smB1[tid] = bih1[r] + bhh1[r];
        smB2[tid] = bih2[r] + bhh2[r];
    }
    if (tid < 256) {
        smC1[tid] = c1_0[cb * HSS + u0 + ul];
        smC2[tid] = c2_0[cb * HSS + u0 + ul];
    }
    __syncthreads();

    // ---- ctx0 = attend(h2_0) ----
    if (bid < BB)
        attend_block(smWS, g_h2T[0], bid, -1, Ws, bs, Wout, bout, outputs_length, out);
    gridbar();

    for (int t = 0; t < TT; ++t) {
        const int p = t & 1;
        const float* h1rT = g_h1T[p];
        float*       h1wT = g_h1T[1 - p];
        const float* h2rT = g_h2T[p];
        float*       h2wT = g_h2T[1 - p];

        // ================= phase A: lstm1 gates + cell1 =================
        {
            u64 acc[4][2] = {};
            const float* embt = g_embT + (size_t)t * EE * BB;
            gemm_region(embt,              max(k0A, 0),   min(k1A, 256), smW1, jl0, b0, acc);
            gemm_region(g_ctxT - 256 * BB, max(k0A, 256), min(k1A, 384), smW1, jl0, b0, acc);
            gemm_region(h1rT   - 384 * BB, max(k0A, 384), min(k1A, 896), smW1, jl0, b0, acc);
            #pragma unroll
            for (int i = 0; i < 4; ++i)
                *reinterpret_cast<ulonglong2*>(&smPart[ksp * PSSZ + (jl0 + i) * PSTR + b0]) =
                    make_ulonglong2(acc[i][0], acc[i][1]);
        }
        __syncthreads();
        if (tid < 256) {   // cell1
            float g[4];
            #pragma unroll
            for (int gate = 0; gate < 4; ++gate) {
                int jj = gate * 4 + ul;
                float s = smB1[jj];
                #pragma unroll
                for (int s2 = 0; s2 < NKSP; ++s2) s += smPart[s2 * PSSZ + jj * PSTR + cb];
                g[gate] = s;
            }
            float cp = smC1[tid];
            float cn = sigf(g[1]) * cp + sigf(g[0]) * tanhf(g[2]);
            float hn = sigf(g[3]) * tanhf(cn);
            smC1[tid] = cn;
            h1wT[(size_t)(u0 + ul) * BB + cb] = hn;   // coalesced
        }
        gridbar();

        // ================= phase B: lstm2 gates + cell2 =================
        {
            u64 acc[4][2] = {};
            gemm_region(h1wT,            max(k0B, 0),   min(k1B, 512),  smW2, jl0, b0, acc);
            gemm_region(h2rT - 512 * BB, max(k0B, 512), min(k1B, 1024), smW2, jl0, b0, acc);
            #pragma unroll
            for (int i = 0; i < 4; ++i)
                *reinterpret_cast<ulonglong2*>(&smPart[ksp * PSSZ + (jl0 + i) * PSTR + b0]) =
                    make_ulonglong2(acc[i][0], acc[i][1]);
        }
        __syncthreads();
        if (tid < 256) {   // cell2
            float g[4];
            #pragma unroll
            for (int gate = 0; gate < 4; ++gate) {
                int jj = gate * 4 + ul;
                float s = smB2[jj];
                #pragma unroll
                for (int s2 = 0; s2 < NKSP; ++s2) s += smPart[s2 * PSSZ + jj * PSTR + cb];
                g[gate] = s;
            }
            float cp = smC2[tid];
            float cn = sigf(g[1]) * cp + sigf(g[0]) * tanhf(g[2]);
            float hn = sigf(g[3]) * tanhf(cn);
            smC2[tid] = cn;
            h2wT[(size_t)(u0 + ul) * BB + cb] = hn;
        }
        gridbar();

        // ================= phase C: attend + logits =================
        if (bid < BB)
            attend_block(smWS, h2wT, bid, t, Ws, bs, Wout, bout, outputs_length, out);
        gridbar();
    }
}

// ---------------- launch ----------------
extern "C" void kernel_launch(void* const* d_in, const int* in_sizes, int n_in,
                              void* d_out, int out_size) {
    const float* listener       = (const float*)d_in[0];
    const int*   outputs_length = (const int*)  d_in[1];
    const int*   targets        = (const int*)  d_in[2];
    const float* embed = (const float*)d_in[4];
    const float* Ws    = (const float*)d_in[5];
    const float* bs    = (const float*)d_in[6];
    const float* Wh    = (const float*)d_in[7];
    const float* bh    = (const float*)d_in[8];
    const float* Wv    = (const float*)d_in[9];
    const float* bv    = (const float*)d_in[10];
    const float* Wih1  = (const float*)d_in[11];
    const float* bih1  = (const float*)d_in[12];
    const float* Whh1  = (const float*)d_in[13];
    const float* bhh1  = (const float*)d_in[14];
    const float* Wih2  = (const float*)d_in[15];
    const float* bih2  = (const float*)d_in[16];
    const float* Whh2  = (const float*)d_in[17];
    const float* bhh2  = (const float*)d_in[18];
    const float* Wout  = (const float*)d_in[19];
    const float* bout  = (const float*)d_in[20];
    const float* h1_0  = (const float*)d_in[21];
    const float* c1_0  = (const float*)d_in[22];
    const float* h2_0  = (const float*)d_in[23];
    const float* c2_0  = (const float*)d_in[24];
    float* out = (float*)d_out;

    cudaFuncSetAttribute(speller_persistent,
                         cudaFuncAttributeMaxDynamicSharedMemorySize, SMEM_BYTES);

    init_kernel<<<(BB * HSS + 255) / 256, 256>>>(h1_0, h2_0);
    embT_kernel<<<TT, 256>>>(targets, embed);
    precompute_kernel<<<dim3(16, 2, 64), 256>>>(listener, Wh, bh, Wv, bv);
    speller_persistent<<<NBLK, NTHR, SMEM_BYTES>>>(
        Wih1, bih1, Whh1, bhh1,
        Wih2, bih2, Whh2, bhh2,
        Ws, bs, Wout, bout,
        outputs_length, c1_0, c2_0, out);
}